// round 7
// baseline (speedup 1.0000x reference)
#include <cuda_runtime.h>
#include <cstdint>

#define Bb 64
#define Nn 64
#define KDIM 512
#define NOUT 480           // NT*SEM = 30*16
#define NT 30
#define NSPAN 2016
#define NP1 65
#define MROWS (Bb * NP1)   // 4160

// Scratch — __device__ globals (no allocation allowed)
__device__ float g_ecum[MROWS * KDIM];     // 8.5 MB  cumsum of word embeddings
__device__ float g_prefix[MROWS * NOUT];   // 8.0 MB  prefix of h

// ---------------------------------------------------------------------------
// Kernel 0: masked cumsum of word embeddings.
// Ecum[b, n] = sum_{i<n, i<len} emb[x[b,i]]   (512-dim), rows m = b*65+n.
// ---------------------------------------------------------------------------
__global__ __launch_bounds__(128) void cumsum_kernel(
    const int* __restrict__ x, const int* __restrict__ lengths,
    const float* __restrict__ emb)
{
    const int b = blockIdx.x;
    const int d = blockIdx.y * 128 + threadIdx.x;
    __shared__ int xr[Nn];
    __shared__ int slen;
    if (threadIdx.x < Nn) xr[threadIdx.x] = x[b * Nn + threadIdx.x];
    if (threadIdx.x == 0) slen = lengths[b];
    __syncthreads();
    const int len = slen;

    float acc = 0.0f;
    g_ecum[(size_t)(b * NP1) * KDIM + d] = 0.0f;
    for (int n0 = 0; n0 < Nn; n0 += 8) {
        float v[8];
#pragma unroll
        for (int j = 0; j < 8; j++)
            v[j] = emb[(size_t)xr[n0 + j] * KDIM + d];
#pragma unroll
        for (int j = 0; j < 8; j++) {
            if (n0 + j < len) acc += v[j];
            g_ecum[(size_t)(b * NP1 + n0 + j + 1) * KDIM + d] = acc;
        }
    }
}

// ---------------------------------------------------------------------------
// Kernel 1: GEMM  g_prefix = Ecum @ w_out^T + min(n,len)*b_out
// BM=64 (65 blocks, M=4160), BN=120 (4 blocks) -> 260 blocks: SINGLE WAVE
// at 2 blocks/SM. 192 threads, thread tile 4 m-pairs x 5 n, FFMA2 with
// pre-duplicated b operand in smem. Double-buffered, 1 barrier per k-tile.
// ---------------------------------------------------------------------------
#define BM 64
#define BN 120
#define BK 16
#define GTH 192
#define ASTRIDE 68
#define NKT (KDIM / BK)    // 32

__device__ __forceinline__ unsigned long long dup2(float f) {
    const unsigned u = __float_as_uint(f);
    return ((unsigned long long)u << 32) | u;
}

__global__ __launch_bounds__(GTH, 2) void gemm_kernel(
    const float* __restrict__ ecum, const float* __restrict__ w,
    const float* __restrict__ bo, const int* __restrict__ lengths)
{
    __shared__ __align__(16) float As[2][BK][ASTRIDE];              // [st][k][m]
    __shared__ unsigned long long Wt[2][BK][5][24];                 // dup'd b

    const int tid = threadIdx.x;
    const int m0 = blockIdx.x * BM;
    const int n0 = blockIdx.y * BN;

    const int tx = tid % 24;   // n group: cols tx*5 .. tx*5+4
    const int ty = tid / 24;   // m group: rows ty*8 (4 pairs)

    // A loader (dense rows now): 256 float4 per tile
    const int am = tid >> 2, akq = tid & 3;
    const bool a2 = (tid < 64);
    const float* aptr0 = ecum + (size_t)(m0 + am) * KDIM + akq * 4;
    const float* aptr1 = ecum + (size_t)(m0 + (a2 ? am + 48 : am)) * KDIM + akq * 4;

    // W loader: 480 float4 per tile -> 2.5/thread (3rd slot for tid<96)
    const int wr0 = tid >> 2,          wq0 = tid & 3;
    const int wr1 = (tid + 192) >> 2,  wq1 = (tid + 192) & 3;
    const bool w2 = (tid < 96);
    const int wr2 = w2 ? ((tid + 384) >> 2) : wr0;
    const int wq2 = w2 ? ((tid + 384) & 3) : wq0;
    const float* wptr0 = w + (size_t)(n0 + wr0) * KDIM + wq0 * 4;
    const float* wptr1 = w + (size_t)(n0 + wr1) * KDIM + wq1 * 4;
    const float* wptr2 = w + (size_t)(n0 + wr2) * KDIM + wq2 * 4;
    const int wtx0 = wr0 / 5, wj0 = wr0 % 5;
    const int wtx1 = wr1 / 5, wj1 = wr1 % 5;
    const int wtx2 = wr2 / 5, wj2 = wr2 % 5;

    float4 av0, av1, wv0, wv1, wv2;

#define FETCH(KT)                                                  \
    do {                                                           \
        av0 = *(const float4*)(aptr0 + (KT) * BK);                 \
        av1 = *(const float4*)(aptr1 + (KT) * BK);                 \
        wv0 = *(const float4*)(wptr0 + (KT) * BK);                 \
        wv1 = *(const float4*)(wptr1 + (KT) * BK);                 \
        wv2 = *(const float4*)(wptr2 + (KT) * BK);                 \
    } while (0)

#define STORE(ST)                                                  \
    do {                                                           \
        As[ST][akq * 4 + 0][am] = av0.x;                           \
        As[ST][akq * 4 + 1][am] = av0.y;                           \
        As[ST][akq * 4 + 2][am] = av0.z;                           \
        As[ST][akq * 4 + 3][am] = av0.w;                           \
        if (a2) {                                                  \
            As[ST][akq * 4 + 0][am + 48] = av1.x;                  \
            As[ST][akq * 4 + 1][am + 48] = av1.y;                  \
            As[ST][akq * 4 + 2][am + 48] = av1.z;                  \
            As[ST][akq * 4 + 3][am + 48] = av1.w;                  \
        }                                                          \
        Wt[ST][wq0 * 4 + 0][wj0][wtx0] = dup2(wv0.x);              \
        Wt[ST][wq0 * 4 + 1][wj0][wtx0] = dup2(wv0.y);              \
        Wt[ST][wq0 * 4 + 2][wj0][wtx0] = dup2(wv0.z);              \
        Wt[ST][wq0 * 4 + 3][wj0][wtx0] = dup2(wv0.w);              \
        Wt[ST][wq1 * 4 + 0][wj1][wtx1] = dup2(wv1.x);              \
        Wt[ST][wq1 * 4 + 1][wj1][wtx1] = dup2(wv1.y);              \
        Wt[ST][wq1 * 4 + 2][wj1][wtx1] = dup2(wv1.z);              \
        Wt[ST][wq1 * 4 + 3][wj1][wtx1] = dup2(wv1.w);              \
        if (w2) {                                                  \
            Wt[ST][wq2 * 4 + 0][wj2][wtx2] = dup2(wv2.x);          \
            Wt[ST][wq2 * 4 + 1][wj2][wtx2] = dup2(wv2.y);          \
            Wt[ST][wq2 * 4 + 2][wj2][wtx2] = dup2(wv2.z);          \
            Wt[ST][wq2 * 4 + 3][wj2][wtx2] = dup2(wv2.w);          \
        }                                                          \
    } while (0)

    unsigned long long acc[4][5];
#pragma unroll
    for (int p = 0; p < 4; p++)
#pragma unroll
        for (int j = 0; j < 5; j++) acc[p][j] = 0ull;

#define COMPUTE(ST)                                                          \
    do {                                                                     \
        _Pragma("unroll")                                                    \
        for (int k = 0; k < BK; k++) {                                       \
            const ulonglong2* ap = (const ulonglong2*)&As[ST][k][ty * 8];    \
            const ulonglong2 a01 = ap[0];                                    \
            const ulonglong2 a23 = ap[1];                                    \
            unsigned long long a[4] = {a01.x, a01.y, a23.x, a23.y};          \
            const unsigned long long* bp = &Wt[ST][k][0][tx];                \
            unsigned long long bd[5];                                        \
            _Pragma("unroll")                                                \
            for (int j = 0; j < 5; j++) bd[j] = bp[j * 24];                  \
            _Pragma("unroll")                                                \
            for (int p = 0; p < 4; p++)                                      \
                _Pragma("unroll")                                            \
                for (int j = 0; j < 5; j++)                                  \
                    asm("fma.rn.f32x2 %0, %1, %2, %0;"                       \
                        : "+l"(acc[p][j]) : "l"(a[p]), "l"(bd[j]));          \
        }                                                                    \
    } while (0)

    FETCH(0);
    STORE(0);
    FETCH(1);
    __syncthreads();

#pragma unroll 1
    for (int kt = 0; kt < NKT - 1; kt++) {
        STORE((kt + 1) & 1);
        if (kt < NKT - 2) FETCH(kt + 2);
        COMPUTE(kt & 1);
        __syncthreads();
    }
    COMPUTE((NKT - 1) & 1);

    // Epilogue: prefix = acc + min(n, len)*bias
    float bb[5];
#pragma unroll
    for (int j = 0; j < 5; j++) bb[j] = bo[n0 + tx * 5 + j];

#pragma unroll
    for (int p = 0; p < 4; p++) {
        unsigned lo[5], hi[5];
#pragma unroll
        for (int j = 0; j < 5; j++)
            asm("mov.b64 {%0, %1}, %2;" : "=r"(lo[j]), "=r"(hi[j]) : "l"(acc[p][j]));
        const int row0 = m0 + ty * 8 + 2 * p;
#pragma unroll
        for (int h = 0; h < 2; h++) {
            const int row = row0 + h;
            const int b = row / NP1;
            const int n = row - b * NP1;
            const int len = lengths[b];
            const float cf = (float)(n < len ? n : len);
            float* op = g_prefix + (size_t)row * NOUT + n0 + tx * 5;
#pragma unroll
            for (int j = 0; j < 5; j++) {
                const float v = __uint_as_float(h ? hi[j] : lo[j]);
                op[j] = fmaf(cf, bb[j], v);
            }
        }
    }
}

// ---------------------------------------------------------------------------
// Kernel 2: span features + L2 norm, smem-tiled over 8x8 (l, r) tiles.
// ---------------------------------------------------------------------------
#define STH 256

__global__ __launch_bounds__(STH) void span_kernel(float* __restrict__ out)
{
    __shared__ float sL[8][NOUT];
    __shared__ float sR[8][NOUT];

    const int b = blockIdx.y;
    const int t = blockIdx.x;                 // 0..35, t = rt*(rt+1)/2 + lt
    int rt = 0;
    while ((rt + 1) * (rt + 2) / 2 <= t) rt++;
    const int lt = t - rt * (rt + 1) / 2;

    const int tid = threadIdx.x;
    const float* pb = g_prefix + (size_t)b * NP1 * NOUT;

    for (int i4 = tid; i4 < 16 * (NOUT / 4); i4 += STH) {
        const int row = i4 / (NOUT / 4);
        const int pos = i4 % (NOUT / 4);
        const int grow = (row < 8) ? (lt * 8 + row) : (rt * 8 + (row - 8) + 1);
        const float4 v = *(const float4*)(pb + (size_t)grow * NOUT + pos * 4);
        if (row < 8) *(float4*)&sL[row][pos * 4] = v;
        else         *(float4*)&sR[row - 8][pos * 4] = v;
    }
    __syncthreads();

    const int slot = tid / 60;        // 0..3 active, 4 = spare
    const int lane = tid % 60;
    const int base = (slot < 4) ? slot : 0;
    const bool diag = (lt == rt);

#pragma unroll 4
    for (int i = 0; i < 16; i++) {
        const int sp = base + 4 * i;          // 0..63
        const int li = sp & 7;
        const int ri = sp >> 3;

        const float4* Rp = (const float4*)&sR[ri][0];
        const float4* Lp = (const float4*)&sL[li][0];
        const float4 ra = Rp[lane],      la = Lp[lane];
        const float4 rb = Rp[60 + lane], lb = Lp[60 + lane];

        float4 da, db;
        da.x = ra.x - la.x; da.y = ra.y - la.y; da.z = ra.z - la.z; da.w = ra.w - la.w;
        db.x = rb.x - lb.x; db.y = rb.y - lb.y; db.z = rb.z - lb.z; db.w = rb.w - lb.w;

        float sqA = da.x * da.x;
        sqA = fmaf(da.y, da.y, sqA); sqA = fmaf(da.z, da.z, sqA); sqA = fmaf(da.w, da.w, sqA);
        float sqB = db.x * db.x;
        sqB = fmaf(db.y, db.y, sqB); sqB = fmaf(db.z, db.z, sqB); sqB = fmaf(db.w, db.w, sqB);

        sqA += __shfl_xor_sync(0xffffffffu, sqA, 1);
        sqA += __shfl_xor_sync(0xffffffffu, sqA, 2);
        sqB += __shfl_xor_sync(0xffffffffu, sqB, 1);
        sqB += __shfl_xor_sync(0xffffffffu, sqB, 2);

        const float invA = rsqrtf(sqA);
        const float invB = rsqrtf(sqB);

        if (slot < 4 && (!diag || li < ri)) {
            const int l = lt * 8 + li;
            const int r = rt * 8 + ri;
            const int k = r - l;
            const int s = (((k - 1) * (128 - k)) >> 1) + l;
            float* op = out + (size_t)(b * NSPAN + s) * NOUT;
            float4 oa, ob;
            oa.x = da.x * invA; oa.y = da.y * invA; oa.z = da.z * invA; oa.w = da.w * invA;
            ob.x = db.x * invB; ob.y = db.y * invB; ob.z = db.z * invB; ob.w = db.w * invB;
            *(float4*)(op + lane * 4) = oa;
            *(float4*)(op + 240 + lane * 4) = ob;
        }
    }
}

// ---------------------------------------------------------------------------
extern "C" void kernel_launch(void* const* d_in, const int* in_sizes, int n_in,
                              void* d_out, int out_size)
{
    const int*   x       = (const int*)d_in[0];
    const int*   lengths = (const int*)d_in[1];
    const float* emb     = (const float*)d_in[2];
    const float* w_out   = (const float*)d_in[3];
    const float* b_out   = (const float*)d_in[4];
    float* out = (float*)d_out;

    float* ecum;
    cudaGetSymbolAddress((void**)&ecum, g_ecum);

    cumsum_kernel<<<dim3(Bb, KDIM / 128), 128>>>(x, lengths, emb);
    gemm_kernel<<<dim3(MROWS / BM, NOUT / BN), GTH>>>(ecum, w_out, b_out, lengths);
    span_kernel<<<dim3(36, Bb), STH>>>(out);
}

// round 8
// speedup vs baseline: 1.5230x; 1.5230x over previous
#include <cuda_runtime.h>
#include <cuda_bf16.h>
#include <cstdint>

#define Bb 64
#define Nn 64
#define KDIM 512
#define NOUT 480           // NT*SEM = 30*16
#define ROWS 4096
#define NSPAN 2016
#define NP1 65

// Scratch — __device__ globals (no allocation allowed)
__device__ float g_h[ROWS * NOUT];            // 7.86 MB
__device__ float g_prefix[Bb * NP1 * NOUT];   // 7.99 MB

// ---------------------------------------------------------------------------
// Kernel 1: fused gather + GEMM  h = emb[x] @ w_out^T + b_out
// Tensor-core bf16 hi/lo split (3 mma per tile pair), fp32 accumulate.
// BM=128, BN=96, BK=32, 256 threads (8 warps as 4m x 2n), warp tile 32x48.
// ---------------------------------------------------------------------------
#define BM 128
#define BN 96
#define BK 32
#define APITCH 40          // bf16 elems per smem row (conflict-free banks)

__device__ __forceinline__ void split2(float x, float y, unsigned& hi, unsigned& lo) {
    // hi = {bf16(y), bf16(x)} with x in low half
    asm("cvt.rn.bf16x2.f32 %0, %1, %2;" : "=r"(hi) : "f"(y), "f"(x));
    const float rx = x - __uint_as_float(hi << 16);
    const float ry = y - __uint_as_float(hi & 0xffff0000u);
    asm("cvt.rn.bf16x2.f32 %0, %1, %2;" : "=r"(lo) : "f"(ry), "f"(rx));
}

#define MMA_BF16(c, a, b0_, b1_)                                          \
    asm volatile(                                                         \
        "mma.sync.aligned.m16n8k16.row.col.f32.bf16.bf16.f32 "            \
        "{%0,%1,%2,%3}, {%4,%5,%6,%7}, {%8,%9}, {%0,%1,%2,%3};"           \
        : "+f"((c)[0]), "+f"((c)[1]), "+f"((c)[2]), "+f"((c)[3])          \
        : "r"((a)[0]), "r"((a)[1]), "r"((a)[2]), "r"((a)[3]),             \
          "r"(b0_), "r"(b1_))

__global__ __launch_bounds__(256, 2) void gemm_kernel(
    const int* __restrict__ x, const float* __restrict__ emb,
    const float* __restrict__ w, const float* __restrict__ bo)
{
    __shared__ __align__(16) __nv_bfloat16 sAhi[BM * APITCH];
    __shared__ __align__(16) __nv_bfloat16 sAlo[BM * APITCH];
    __shared__ __align__(16) __nv_bfloat16 sWhi[BN * APITCH];
    __shared__ __align__(16) __nv_bfloat16 sWlo[BN * APITCH];
    __shared__ int rowidx[BM];

    const int tid = threadIdx.x;
    const int m0 = blockIdx.x * BM;
    const int n0 = blockIdx.y * BN;

    if (tid < BM) rowidx[tid] = x[m0 + tid];
    __syncthreads();

    // ---- loader mappings (fixed rows per thread) ----
    // A tile: 128 rows x 32 k = 1024 float4; 4 per thread
    int arow[4];
    const float* aptr[4];
#pragma unroll
    for (int i = 0; i < 4; i++) {
        const int idx = tid + 256 * i;
        arow[i] = idx >> 3;
        const int kq = idx & 7;
        aptr[i] = emb + (size_t)rowidx[arow[i]] * KDIM + kq * 4;
    }
    // W tile: 96 rows x 32 k = 768 float4; 3 per thread
    int wrow[3];
    const float* wptr[3];
#pragma unroll
    for (int i = 0; i < 3; i++) {
        const int idx = tid + 256 * i;
        wrow[i] = idx >> 3;
        wptr[i] = w + (size_t)(n0 + wrow[i]) * KDIM + (idx & 7) * 4;
    }

    const int lane = tid & 31;
    const int grp = lane >> 2;
    const int qid = lane & 3;
    const int warpid = tid >> 5;
    const int wm = warpid & 3;   // m quadrant: rows wm*32
    const int wn = warpid >> 2;  // n half: cols wn*48

    const int aoff = (wm * 32 + grp) * APITCH + qid * 2;   // bf16 units
    const int boff = (wn * 48 + grp) * APITCH + qid * 2;

    float acc[2][6][4];
#pragma unroll
    for (int ma = 0; ma < 2; ma++)
#pragma unroll
        for (int j = 0; j < 6; j++)
#pragma unroll
            for (int c = 0; c < 4; c++) acc[ma][j][c] = 0.0f;

    for (int kt = 0; kt < KDIM / BK; kt++) {
        // fetch globals (overlaps previous compute until first use)
        float4 va[4], vw[3];
#pragma unroll
        for (int i = 0; i < 4; i++) va[i] = *(const float4*)(aptr[i] + kt * BK);
#pragma unroll
        for (int i = 0; i < 3; i++) vw[i] = *(const float4*)(wptr[i] + kt * BK);

        __syncthreads();   // previous compute done before smem overwrite

#pragma unroll
        for (int i = 0; i < 4; i++) {
            const int idx = tid + 256 * i;
            const int off = (idx >> 3) * APITCH + (idx & 7) * 4;
            uint2 h, l;
            split2(va[i].x, va[i].y, h.x, l.x);
            split2(va[i].z, va[i].w, h.y, l.y);
            *(uint2*)(sAhi + off) = h;
            *(uint2*)(sAlo + off) = l;
        }
#pragma unroll
        for (int i = 0; i < 3; i++) {
            const int idx = tid + 256 * i;
            const int off = (idx >> 3) * APITCH + (idx & 7) * 4;
            uint2 h, l;
            split2(vw[i].x, vw[i].y, h.x, l.x);
            split2(vw[i].z, vw[i].w, h.y, l.y);
            *(uint2*)(sWhi + off) = h;
            *(uint2*)(sWlo + off) = l;
        }
        __syncthreads();

#pragma unroll
        for (int kb = 0; kb < BK; kb += 16) {
            unsigned ah[2][4], al[2][4];
#pragma unroll
            for (int ma = 0; ma < 2; ma++) {
                const int base = aoff + ma * 16 * APITCH + kb;
                ah[ma][0] = *(const unsigned*)(sAhi + base);
                ah[ma][1] = *(const unsigned*)(sAhi + base + 8 * APITCH);
                ah[ma][2] = *(const unsigned*)(sAhi + base + 8);
                ah[ma][3] = *(const unsigned*)(sAhi + base + 8 * APITCH + 8);
                al[ma][0] = *(const unsigned*)(sAlo + base);
                al[ma][1] = *(const unsigned*)(sAlo + base + 8 * APITCH);
                al[ma][2] = *(const unsigned*)(sAlo + base + 8);
                al[ma][3] = *(const unsigned*)(sAlo + base + 8 * APITCH + 8);
            }
#pragma unroll
            for (int j = 0; j < 6; j++) {
                const int bbase = boff + j * 8 * APITCH + kb;
                const unsigned bh0 = *(const unsigned*)(sWhi + bbase);
                const unsigned bh1 = *(const unsigned*)(sWhi + bbase + 8);
                const unsigned bl0 = *(const unsigned*)(sWlo + bbase);
                const unsigned bl1 = *(const unsigned*)(sWlo + bbase + 8);
#pragma unroll
                for (int ma = 0; ma < 2; ma++) {
                    MMA_BF16(acc[ma][j], ah[ma], bh0, bh1);
                    MMA_BF16(acc[ma][j], ah[ma], bl0, bl1);
                    MMA_BF16(acc[ma][j], al[ma], bh0, bh1);
                }
            }
        }
    }

    // Epilogue: add bias, store fp32 h
#pragma unroll
    for (int j = 0; j < 6; j++) {
        const int col = n0 + wn * 48 + j * 8 + qid * 2;
        const float2 bj = *(const float2*)(bo + col);
#pragma unroll
        for (int ma = 0; ma < 2; ma++) {
            const int row0 = m0 + wm * 32 + ma * 16 + grp;
            float2 v0, v1;
            v0.x = acc[ma][j][0] + bj.x;
            v0.y = acc[ma][j][1] + bj.y;
            v1.x = acc[ma][j][2] + bj.x;
            v1.y = acc[ma][j][3] + bj.y;
            *(float2*)(g_h + (size_t)row0 * NOUT + col) = v0;
            *(float2*)(g_h + (size_t)(row0 + 8) * NOUT + col) = v1;
        }
    }
}

// ---------------------------------------------------------------------------
// Kernel 2: masked cumsum over sequence -> prefix [B, N+1, 480]
// ---------------------------------------------------------------------------
__global__ __launch_bounds__(120) void prefix_kernel(const int* __restrict__ lengths)
{
    const int b = blockIdx.y;
    const int o = blockIdx.x * 120 + threadIdx.x;
    const int len = lengths[b];
    float acc = 0.0f;
    g_prefix[((size_t)b * NP1 + 0) * NOUT + o] = 0.0f;
#pragma unroll 8
    for (int n = 0; n < Nn; n++) {
        const float v = g_h[((size_t)b * Nn + n) * NOUT + o];
        if (n < len) acc += v;
        g_prefix[((size_t)b * NP1 + n + 1) * NOUT + o] = acc;
    }
}

// ---------------------------------------------------------------------------
// Kernel 3: span features + L2 norm, smem-tiled over 8x8 (l, r) tiles.
// ---------------------------------------------------------------------------
#define STH 256

__global__ __launch_bounds__(STH) void span_kernel(float* __restrict__ out)
{
    __shared__ float sL[8][NOUT];
    __shared__ float sR[8][NOUT];

    const int b = blockIdx.y;
    const int t = blockIdx.x;                 // 0..35, t = rt*(rt+1)/2 + lt
    int rt = 0;
    while ((rt + 1) * (rt + 2) / 2 <= t) rt++;
    const int lt = t - rt * (rt + 1) / 2;

    const int tid = threadIdx.x;
    const float* pb = g_prefix + (size_t)b * NP1 * NOUT;

    for (int i4 = tid; i4 < 16 * (NOUT / 4); i4 += STH) {
        const int row = i4 / (NOUT / 4);
        const int pos = i4 % (NOUT / 4);
        const int grow = (row < 8) ? (lt * 8 + row) : (rt * 8 + (row - 8) + 1);
        const float4 v = *(const float4*)(pb + (size_t)grow * NOUT + pos * 4);
        if (row < 8) *(float4*)&sL[row][pos * 4] = v;
        else         *(float4*)&sR[row - 8][pos * 4] = v;
    }
    __syncthreads();

    const int slot = tid / 60;        // 0..3 active, 4 = spare
    const int lane = tid % 60;
    const int base = (slot < 4) ? slot : 0;
    const bool diag = (lt == rt);

#pragma unroll 4
    for (int i = 0; i < 16; i++) {
        const int sp = base + 4 * i;          // 0..63
        const int li = sp & 7;
        const int ri = sp >> 3;

        const float4* Rp = (const float4*)&sR[ri][0];
        const float4* Lp = (const float4*)&sL[li][0];
        const float4 ra = Rp[lane],      la = Lp[lane];
        const float4 rb = Rp[60 + lane], lb = Lp[60 + lane];

        float4 da, db;
        da.x = ra.x - la.x; da.y = ra.y - la.y; da.z = ra.z - la.z; da.w = ra.w - la.w;
        db.x = rb.x - lb.x; db.y = rb.y - lb.y; db.z = rb.z - lb.z; db.w = rb.w - lb.w;

        float sqA = da.x * da.x;
        sqA = fmaf(da.y, da.y, sqA); sqA = fmaf(da.z, da.z, sqA); sqA = fmaf(da.w, da.w, sqA);
        float sqB = db.x * db.x;
        sqB = fmaf(db.y, db.y, sqB); sqB = fmaf(db.z, db.z, sqB); sqB = fmaf(db.w, db.w, sqB);

        sqA += __shfl_xor_sync(0xffffffffu, sqA, 1);
        sqA += __shfl_xor_sync(0xffffffffu, sqA, 2);
        sqB += __shfl_xor_sync(0xffffffffu, sqB, 1);
        sqB += __shfl_xor_sync(0xffffffffu, sqB, 2);

        const float invA = rsqrtf(sqA);
        const float invB = rsqrtf(sqB);

        if (slot < 4 && (!diag || li < ri)) {
            const int l = lt * 8 + li;
            const int r = rt * 8 + ri;
            const int k = r - l;
            const int s = (((k - 1) * (128 - k)) >> 1) + l;
            float* op = out + (size_t)(b * NSPAN + s) * NOUT;
            float4 oa, ob;
            oa.x = da.x * invA; oa.y = da.y * invA; oa.z = da.z * invA; oa.w = da.w * invA;
            ob.x = db.x * invB; ob.y = db.y * invB; ob.z = db.z * invB; ob.w = db.w * invB;
            *(float4*)(op + lane * 4) = oa;
            *(float4*)(op + 240 + lane * 4) = ob;
        }
    }
}

// ---------------------------------------------------------------------------
extern "C" void kernel_launch(void* const* d_in, const int* in_sizes, int n_in,
                              void* d_out, int out_size)
{
    const int*   x       = (const int*)d_in[0];
    const int*   lengths = (const int*)d_in[1];
    const float* emb     = (const float*)d_in[2];
    const float* w_out   = (const float*)d_in[3];
    const float* b_out   = (const float*)d_in[4];
    float* out = (float*)d_out;

    gemm_kernel<<<dim3(ROWS / BM, NOUT / BN), 256>>>(x, emb, w_out, b_out);
    prefix_kernel<<<dim3(4, Bb), 120>>>(lengths);
    span_kernel<<<dim3(36, Bb), STH>>>(out);
}